// round 2
// baseline (speedup 1.0000x reference)
#include <cuda_runtime.h>
#include <cstdint>

// ---------------- problem constants ----------------
#define T_ 256
#define B_ 128
#define TB_ 32768           // T_*B_
#define OBS_DIM_ 1604
#define SCALAR_DIM_ 452
#define GRID_FLAT_ 1152     // 2*32*18
#define CNN_FLAT_ 2560      // 64*8*5
#define HID_ 128
#define N_ACT_ 2305
#define EMB_ 192            // 128 + 64

// output layout (flat concat of (logits, values, h_f, c_f))
#define OUT_LOGITS_ 0
#define OUT_VALUES_ ((size_t)TB_ * N_ACT_)                 // 75530240
#define OUT_HF_     (OUT_VALUES_ + TB_)                    // 75563008
#define OUT_CF_     (OUT_HF_ + (size_t)B_ * HID_)          // 75579392

// ---------------- scratch ----------------
__device__ float g_c3[(size_t)TB_ * CNN_FLAT_];   // conv3 flat output
__device__ float g_s1[(size_t)TB_ * 64];          // scalar mlp hidden
__device__ float g_emb[(size_t)TB_ * EMB_];       // [cnn(128) | sc(64)]
__device__ float g_xg[(size_t)TB_ * 512];         // emb @ w_ih.T + b_ih + b_hh
__device__ float g_h[(size_t)TB_ * HID_];         // lstm hidden per step
__device__ float g_whhT[128 * 512];               // transposed w_hh

// ---------------- conv kernel: one block per sample ----------------
// smem layout (floats):
//  w1s:   [0, 576)
//  grid:  [576, 1728)
//  c1:    [1728, 20160)        32x32x18
//  w2s:   [20160, 38592)
//  c2:    [38592, 47808)       64x16x9
//  w3s:   [0, 36864)           (reuses dead conv1-era region)
//  c3:    [47808, 50368)       64x8x5
#define CONV_SMEM_FLOATS 50368

__global__ void __launch_bounds__(256, 1) conv_kernel(
    const float* __restrict__ obs,
    const float* __restrict__ w1, const float* __restrict__ b1,
    const float* __restrict__ w2, const float* __restrict__ b2,
    const float* __restrict__ w3, const float* __restrict__ b3)
{
    extern __shared__ float sm[];
    float* w1s    = sm;
    float* grid_s = sm + 576;
    float* c1s    = sm + 1728;
    float* w2s    = sm + 20160;
    float* c2s    = sm + 38592;
    float* w3s    = sm;
    float* c3s    = sm + 47808;

    const int s   = blockIdx.x;
    const int tid = threadIdx.x;

    // --- stage inputs + conv1/conv2 weights ---
    {
        const float* gsrc = obs + (size_t)s * OBS_DIM_ + SCALAR_DIM_;
        for (int i = tid; i < GRID_FLAT_; i += 256) grid_s[i] = gsrc[i];
        for (int i = tid; i < 576; i += 256) w1s[i] = w1[i];
        const float4* src = (const float4*)w2;
        float4* dst = (float4*)w2s;
        for (int i = tid; i < 4608; i += 256) dst[i] = src[i];
    }
    __syncthreads();

    // --- conv1: 2->32 ch, 3x3 s1 p1, out 32x32x18 ---
    {
        const int oc = tid >> 3;       // 0..31
        const int pg = tid & 7;        // 8 pos-groups of 72
        float w[18];
        #pragma unroll
        for (int q = 0; q < 18; q++) w[q] = w1s[oc * 18 + q];
        const float bias = b1[oc];
        for (int p = pg * 72; p < pg * 72 + 72; p++) {
            const int oy = p / 18, ox = p % 18;
            float acc = bias;
            #pragma unroll
            for (int ic = 0; ic < 2; ic++) {
                #pragma unroll
                for (int ky = 0; ky < 3; ky++) {
                    const int iy = oy + ky - 1;
                    if (iy < 0 || iy >= 32) continue;
                    const float* row = grid_s + ic * 576 + iy * 18;
                    #pragma unroll
                    for (int kx = 0; kx < 3; kx++) {
                        const int ix = ox + kx - 1;
                        if (ix >= 0 && ix < 18) acc += w[ic * 9 + ky * 3 + kx] * row[ix];
                    }
                }
            }
            c1s[oc * 576 + p] = fmaxf(acc, 0.f);
        }
    }
    __syncthreads();

    // --- conv2: 32->64 ch, 3x3 s2 p1, in 32x32x18 -> out 64x16x9 ---
    {
        const int oy  = tid & 15;            // 0..15
        const int oc0 = (tid >> 4) * 4;      // 0..60
        float acc[4][9];
        #pragma unroll
        for (int c = 0; c < 4; c++) {
            const float bv = b2[oc0 + c];
            #pragma unroll
            for (int x = 0; x < 9; x++) acc[c][x] = bv;
        }
        for (int ic = 0; ic < 32; ic++) {
            #pragma unroll
            for (int ky = 0; ky < 3; ky++) {
                const int iy = 2 * oy + ky - 1;      // max 31, only lower bound needed
                if (iy < 0) continue;
                const float* row = c1s + ic * 576 + iy * 18;
                #pragma unroll
                for (int kx = 0; kx < 3; kx++) {
                    float wv[4];
                    #pragma unroll
                    for (int c = 0; c < 4; c++)
                        wv[c] = w2s[((oc0 + c) * 32 + ic) * 9 + ky * 3 + kx];
                    #pragma unroll
                    for (int ox = 0; ox < 9; ox++) {
                        const int ix = 2 * ox + kx - 1;   // max 17, only lower bound
                        const float v = (ix >= 0) ? row[ix] : 0.f;
                        #pragma unroll
                        for (int c = 0; c < 4; c++) acc[c][ox] += wv[c] * v;
                    }
                }
            }
        }
        #pragma unroll
        for (int c = 0; c < 4; c++)
            #pragma unroll
            for (int x = 0; x < 9; x++)
                c2s[(oc0 + c) * 144 + oy * 9 + x] = fmaxf(acc[c][x], 0.f);
    }
    __syncthreads();

    // --- stage conv3 weights (overwrites conv1-era smem) ---
    {
        const float4* src = (const float4*)w3;
        float4* dst = (float4*)w3s;
        for (int i = tid; i < 9216; i += 256) dst[i] = src[i];
    }
    __syncthreads();

    // --- conv3: 64->64 ch, 3x3 s2 p1, in 64x16x9 -> out 64x8x5 ---
    if (tid < 128) {
        const int oy  = tid & 7;             // 0..7
        const int oc0 = (tid >> 3) * 4;      // 0..60
        float acc[4][5];
        #pragma unroll
        for (int c = 0; c < 4; c++) {
            const float bv = b3[oc0 + c];
            #pragma unroll
            for (int x = 0; x < 5; x++) acc[c][x] = bv;
        }
        for (int ic = 0; ic < 64; ic++) {
            #pragma unroll
            for (int ky = 0; ky < 3; ky++) {
                const int iy = 2 * oy + ky - 1;      // max 15, only lower bound
                if (iy < 0) continue;
                const float* row = c2s + ic * 144 + iy * 9;
                #pragma unroll
                for (int kx = 0; kx < 3; kx++) {
                    float wv[4];
                    #pragma unroll
                    for (int c = 0; c < 4; c++)
                        wv[c] = w3s[((oc0 + c) * 64 + ic) * 9 + ky * 3 + kx];
                    #pragma unroll
                    for (int ox = 0; ox < 5; ox++) {
                        const int ix = 2 * ox + kx - 1;   // needs both bounds (max 9)
                        const float v = (ix >= 0 && ix < 9) ? row[ix] : 0.f;
                        #pragma unroll
                        for (int c = 0; c < 4; c++) acc[c][ox] += wv[c] * v;
                    }
                }
            }
        }
        #pragma unroll
        for (int c = 0; c < 4; c++)
            #pragma unroll
            for (int x = 0; x < 5; x++)
                c3s[(oc0 + c) * 40 + oy * 5 + x] = fmaxf(acc[c][x], 0.f);
    }
    __syncthreads();

    // --- write c3 flat ---
    {
        float4* dst = (float4*)(g_c3 + (size_t)s * CNN_FLAT_);
        const float4* src = (const float4*)c3s;
        for (int i = tid; i < 640; i += 256) dst[i] = src[i];
    }
}

// ---------------- generic tiled fp32 GEMM: C = act(A @ B^T + bias [+bias2]) ----------------
// A: [M][lda] row-major (uses K cols), B: [N][K] row-major, C: [M][ldc] (+col offset baked into C ptr)
__global__ void __launch_bounds__(256, 2) gemm_bias_act(
    const float* __restrict__ A, int lda,
    const float* __restrict__ B,
    const float* __restrict__ bias, const float* __restrict__ bias2,
    float* __restrict__ C, int ldc,
    int N, int K, int do_relu)
{
    __shared__ float As[16][132];
    __shared__ float Bs[16][132];
    const int m0 = blockIdx.y * 128;
    const int n0 = blockIdx.x * 128;
    const int tid = threadIdx.x;
    const int tx = tid & 15, ty = tid >> 4;

    float acc[8][8];
    #pragma unroll
    for (int i = 0; i < 8; i++)
        #pragma unroll
        for (int j = 0; j < 8; j++) acc[i][j] = 0.f;

    for (int k0 = 0; k0 < K; k0 += 16) {
        #pragma unroll
        for (int i = 0; i < 8; i++) {
            const int idx = tid + i * 256;
            const int r = idx >> 4, kk = idx & 15;
            const int k = k0 + kk;
            As[kk][r] = (k < K) ? A[(size_t)(m0 + r) * lda + k] : 0.f;
        }
        #pragma unroll
        for (int i = 0; i < 8; i++) {
            const int idx = tid + i * 256;
            const int c = idx >> 4, kk = idx & 15;
            const int k = k0 + kk;
            const int n = n0 + c;
            Bs[kk][c] = (n < N && k < K) ? B[(size_t)n * K + k] : 0.f;
        }
        __syncthreads();
        #pragma unroll
        for (int kk = 0; kk < 16; kk++) {
            float a[8], b[8];
            #pragma unroll
            for (int i = 0; i < 8; i++) a[i] = As[kk][ty * 8 + i];
            #pragma unroll
            for (int j = 0; j < 8; j++) b[j] = Bs[kk][tx * 8 + j];
            #pragma unroll
            for (int i = 0; i < 8; i++)
                #pragma unroll
                for (int j = 0; j < 8; j++) acc[i][j] += a[i] * b[j];
        }
        __syncthreads();
    }

    #pragma unroll
    for (int i = 0; i < 8; i++) {
        const int m = m0 + ty * 8 + i;
        #pragma unroll
        for (int j = 0; j < 8; j++) {
            const int n = n0 + tx * 8 + j;
            if (n < N) {
                float v = acc[i][j] + bias[n];
                if (bias2) v += bias2[n];
                if (do_relu) v = fmaxf(v, 0.f);
                C[(size_t)m * ldc + n] = v;
            }
        }
    }
}

// ---------------- w_hh transpose ----------------
__global__ void transpose_whh(const float* __restrict__ w_hh)
{
    const int t = blockIdx.x * blockDim.x + threadIdx.x;
    if (t >= 512 * 128) return;
    const int g = t >> 7, kk = t & 127;
    g_whhT[kk * 512 + g] = w_hh[g * 128 + kk];
}

// ---------------- LSTM recurrence: one block per batch element ----------------
__device__ __forceinline__ float sigf(float x) { return 1.f / (1.f + __expf(-x)); }

__global__ void __launch_bounds__(512, 1) lstm_kernel(
    const int* __restrict__ done,
    const float* __restrict__ h0, const float* __restrict__ c0,
    float* __restrict__ out_hf, float* __restrict__ out_cf)
{
    __shared__ float hs[128];
    __shared__ float cs[128];
    __shared__ float gs[512];
    const int b = blockIdx.x;
    const int tid = threadIdx.x;

    if (tid < 128) {
        hs[tid] = h0[b * 128 + tid];
        cs[tid] = c0[b * 128 + tid];
    }
    __syncthreads();

    for (int t = 0; t < T_; t++) {
        const float keep = (t == 0) ? 1.f : (done[(t - 1) * B_ + b] ? 0.f : 1.f);
        // gates = xg + keep * (h @ w_hh^T)
        float acc = 0.f;
        const float* wcol = g_whhT + tid;
        #pragma unroll 8
        for (int kk = 0; kk < 128; kk++) acc += wcol[kk * 512] * hs[kk];
        gs[tid] = g_xg[((size_t)(t * B_) + b) * 512 + tid] + keep * acc;
        __syncthreads();
        if (tid < 128) {
            const float ig = sigf(gs[tid]);
            const float fg = sigf(gs[tid + 128]);
            const float gg = tanhf(gs[tid + 256]);
            const float og = sigf(gs[tid + 384]);
            const float cn = fg * (cs[tid] * keep) + ig * gg;
            const float hn = og * tanhf(cn);
            cs[tid] = cn;
            hs[tid] = hn;
            g_h[((size_t)(t * B_) + b) * 128 + tid] = hn;
        }
        __syncthreads();
    }
    if (tid < 128) {
        out_hf[b * 128 + tid] = hs[tid];
        out_cf[b * 128 + tid] = cs[tid];
    }
}

// ---------------- values head: one warp per sample ----------------
__global__ void values_kernel(const float* __restrict__ vw, const float* __restrict__ vb,
                              float* __restrict__ out)
{
    const int warp = (blockIdx.x * blockDim.x + threadIdx.x) >> 5;
    const int lane = threadIdx.x & 31;
    if (warp >= TB_) return;
    const float* h = g_h + (size_t)warp * 128;
    float p = 0.f;
    #pragma unroll
    for (int i = 0; i < 4; i++) p += h[lane + i * 32] * vw[lane + i * 32];
    #pragma unroll
    for (int o = 16; o > 0; o >>= 1) p += __shfl_xor_sync(0xffffffffu, p, o);
    if (lane == 0) out[warp] = p + vb[0];
}

// ---------------- launch ----------------
extern "C" void kernel_launch(void* const* d_in, const int* in_sizes, int n_in,
                              void* d_out, int out_size)
{
    const float* obs    = (const float*)d_in[0];
    const float* h0     = (const float*)d_in[1];
    const float* c0     = (const float*)d_in[2];
    const int*   done   = (const int*)d_in[3];
    const float* conv1w = (const float*)d_in[4];
    const float* conv1b = (const float*)d_in[5];
    const float* conv2w = (const float*)d_in[6];
    const float* conv2b = (const float*)d_in[7];
    const float* conv3w = (const float*)d_in[8];
    const float* conv3b = (const float*)d_in[9];
    const float* fcw    = (const float*)d_in[10];
    const float* fcb    = (const float*)d_in[11];
    const float* s1w    = (const float*)d_in[12];
    const float* s1b    = (const float*)d_in[13];
    const float* s2w    = (const float*)d_in[14];
    const float* s2b    = (const float*)d_in[15];
    const float* wih    = (const float*)d_in[16];
    const float* whh    = (const float*)d_in[17];
    const float* bih    = (const float*)d_in[18];
    const float* bhh    = (const float*)d_in[19];
    const float* polw   = (const float*)d_in[20];
    const float* polb   = (const float*)d_in[21];
    const float* valw   = (const float*)d_in[22];
    const float* valb   = (const float*)d_in[23];
    float* out = (float*)d_out;

    float *p_c3, *p_s1, *p_emb, *p_xg, *p_h;
    cudaGetSymbolAddress((void**)&p_c3, g_c3);
    cudaGetSymbolAddress((void**)&p_s1, g_s1);
    cudaGetSymbolAddress((void**)&p_emb, g_emb);
    cudaGetSymbolAddress((void**)&p_xg, g_xg);
    cudaGetSymbolAddress((void**)&p_h, g_h);

    // conv stack (bulk of the work)
    cudaFuncSetAttribute(conv_kernel, cudaFuncAttributeMaxDynamicSharedMemorySize,
                         CONV_SMEM_FLOATS * 4);
    conv_kernel<<<TB_, 256, CONV_SMEM_FLOATS * 4>>>(obs, conv1w, conv1b, conv2w, conv2b,
                                                    conv3w, conv3b);

    // scalar MLP: s1 (K=452, from strided obs) then s2 -> emb cols [128,192)
    gemm_bias_act<<<dim3(1, TB_ / 128), 256>>>(obs, OBS_DIM_, s1w, s1b, nullptr,
                                               p_s1, 64, 64, SCALAR_DIM_, 1);
    gemm_bias_act<<<dim3(1, TB_ / 128), 256>>>(p_s1, 64, s2w, s2b, nullptr,
                                               p_emb + 128, EMB_, 64, 64, 1);

    // fc: c3 -> emb cols [0,128)
    gemm_bias_act<<<dim3(1, TB_ / 128), 256>>>(p_c3, CNN_FLAT_, fcw, fcb, nullptr,
                                               p_emb, EMB_, 128, CNN_FLAT_, 1);

    // xg = emb @ w_ih^T + b_ih + b_hh
    gemm_bias_act<<<dim3(4, TB_ / 128), 256>>>(p_emb, EMB_, wih, bih, bhh,
                                               p_xg, 512, 512, EMB_, 0);

    // recurrence
    transpose_whh<<<(512 * 128 + 255) / 256, 256>>>(whh);
    lstm_kernel<<<B_, 512>>>(done, h0, c0, out + OUT_HF_, out + OUT_CF_);

    // heads
    gemm_bias_act<<<dim3((N_ACT_ + 127) / 128, TB_ / 128), 256>>>(
        p_h, HID_, polw, polb, nullptr, out + OUT_LOGITS_, N_ACT_, N_ACT_, HID_, 0);
    values_kernel<<<TB_ / 8, 256>>>(valw, valb, out + OUT_VALUES_);
}

// round 15
// speedup vs baseline: 1.4930x; 1.4930x over previous
#include <cuda_runtime.h>
#include <cstdint>

// ---------------- problem constants ----------------
#define T_ 256
#define B_ 128
#define TB_ 32768           // T_*B_
#define OBS_DIM_ 1604
#define SCALAR_DIM_ 452
#define GRID_FLAT_ 1152     // 2*32*18
#define CNN_FLAT_ 2560      // 64*8*5
#define HID_ 128
#define N_ACT_ 2305
#define EMB_ 192            // 128 + 64

// output layout (flat concat of (logits, values, h_f, c_f))
#define OUT_LOGITS_ 0
#define OUT_VALUES_ ((size_t)TB_ * N_ACT_)
#define OUT_HF_     (OUT_VALUES_ + TB_)
#define OUT_CF_     (OUT_HF_ + (size_t)B_ * HID_)

// ---------------- scratch ----------------
__device__ float g_c3[(size_t)TB_ * CNN_FLAT_];   // conv3 flat output
__device__ float g_s1[(size_t)TB_ * 64];          // scalar mlp hidden
__device__ float g_emb[(size_t)TB_ * EMB_];       // [cnn(128) | sc(64)]
__device__ float g_xg[(size_t)TB_ * 512];         // emb @ w_ih.T + b_ih + b_hh
__device__ float g_h[(size_t)TB_ * HID_];         // lstm hidden per step
__device__ float g_whhT[128 * 512];               // transposed w_hh [k][gate]
__device__ float g_w2t[18432];                    // conv2 w in [ic][ky][kx][oc]
__device__ float g_w3t[36864];                    // conv3 w in [ic][ky][kx][oc]

// ---------------- weight re-layout kernels ----------------
__global__ void transpose_w2(const float* __restrict__ w2)
{
    const int t = blockIdx.x * 256 + threadIdx.x;
    if (t >= 18432) return;
    const int oc = t & 63;
    const int q  = t >> 6;          // ic*9 + ky*3 + kx
    const int ic = q / 9, kk = q % 9;
    g_w2t[t] = w2[(oc * 32 + ic) * 9 + kk];
}

__global__ void transpose_w3(const float* __restrict__ w3)
{
    const int t = blockIdx.x * 256 + threadIdx.x;
    if (t >= 36864) return;
    const int oc = t & 63;
    const int q  = t >> 6;
    const int ic = q / 9, kk = q % 9;
    g_w3t[t] = w3[(oc * 64 + ic) * 9 + kk];
}

__global__ void transpose_whh(const float* __restrict__ w_hh)
{
    const int t = blockIdx.x * blockDim.x + threadIdx.x;
    if (t >= 512 * 128) return;
    const int g = t >> 7, kk = t & 127;
    g_whhT[kk * 512 + g] = w_hh[g * 128 + kk];
}

// ---------------- conv kernel: one block of 512 per sample ----------------
// smem float layout:
//  c1s:    [0, 19456)        32 ch x 32 rows x 19 (col0 = zero halo)
//  w2s:    [19456, 37888)    [ic][ky][kx][oc]  (18432)
//  c2s:    [37888, 49152)    64 ch x 16 rows x 11 (col0, col10 = zero halo)
//  c3s:    [49152, 51712)    64 x 8 x 5
//  grid_s: [51712, 52992)    2 ch x 32 rows x 20 (col0, col19 = zero halo)
//  w1s:    [52992, 53568)
//  w3s:    [0, 36864)        reuses c1s+w2s region after conv2
#define CONV_SMEM_FLOATS 53568

__global__ void __launch_bounds__(512, 1) conv_kernel(
    const float* __restrict__ obs,
    const float* __restrict__ w1, const float* __restrict__ b1,
    const float* __restrict__ b2, const float* __restrict__ b3)
{
    extern __shared__ float sm[];
    float* c1s    = sm;
    float* w2s    = sm + 19456;
    float* c2s    = sm + 37888;
    float* c3s    = sm + 49152;
    float* grid_s = sm + 51712;
    float* w1s    = sm + 52992;
    float* w3s    = sm;

    const int s   = blockIdx.x;
    const int tid = threadIdx.x;

    // --- zero halos + stage inputs/weights ---
    for (int i = tid; i < 64; i += 512)   { grid_s[i * 20] = 0.f; grid_s[i * 20 + 19] = 0.f; }
    for (int i = tid; i < 1024; i += 512) c1s[i * 19] = 0.f;
    for (int i = tid; i < 1024; i += 512) { c2s[i * 11] = 0.f; c2s[i * 11 + 10] = 0.f; }

    {
        const float* gsrc = obs + (size_t)s * OBS_DIM_ + SCALAR_DIM_;
        for (int i = tid; i < GRID_FLAT_; i += 512) {
            const int c = i / 576, rem = i % 576;
            const int y = rem / 18, x = rem % 18;
            grid_s[(c * 32 + y) * 20 + x + 1] = gsrc[i];
        }
        for (int i = tid; i < 576; i += 512) w1s[i] = w1[i];
        const float4* src = (const float4*)g_w2t;
        float4* dst = (float4*)w2s;
        for (int i = tid; i < 4608; i += 512) dst[i] = src[i];
    }
    __syncthreads();

    // --- conv1: 2->32 ch, 3x3 s1 p1, out 32x(32x18) ---
    {
        const int oc = tid >> 4;        // 0..31
        const int rg = tid & 15;        // row pair
        float w[18];
        #pragma unroll
        for (int q = 0; q < 18; q++) w[q] = w1s[oc * 18 + q];
        const float bias = b1[oc];
        #pragma unroll
        for (int dy = 0; dy < 2; dy++) {
            const int oy = rg * 2 + dy;
            float acc[18];
            #pragma unroll
            for (int x = 0; x < 18; x++) acc[x] = bias;
            #pragma unroll
            for (int ic = 0; ic < 2; ic++) {
                #pragma unroll
                for (int ky = 0; ky < 3; ky++) {
                    const int iy = oy + ky - 1;
                    if (iy < 0 || iy > 31) continue;
                    const float* row = grid_s + (ic * 32 + iy) * 20;
                    float r[20];
                    #pragma unroll
                    for (int j = 0; j < 20; j++) r[j] = row[j];
                    #pragma unroll
                    for (int kx = 0; kx < 3; kx++) {
                        const float wv = w[ic * 9 + ky * 3 + kx];
                        #pragma unroll
                        for (int ox = 0; ox < 18; ox++) acc[ox] += wv * r[ox + kx];
                    }
                }
            }
            float* orow = c1s + (oc * 32 + oy) * 19;
            #pragma unroll
            for (int ox = 0; ox < 18; ox++) orow[ox + 1] = fmaxf(acc[ox], 0.f);
        }
    }
    __syncthreads();

    // --- conv2: 32->64 ch, 3x3 s2 p1 -> 64x(16x9). thread = (oc pair, oy) ---
    {
        const int oc0 = (tid >> 4) * 2;   // 0..62
        const int oy  = tid & 15;
        float acc[2][9];
        {
            const float b0 = b2[oc0], b1v = b2[oc0 + 1];
            #pragma unroll
            for (int x = 0; x < 9; x++) { acc[0][x] = b0; acc[1][x] = b1v; }
        }
        for (int ic = 0; ic < 32; ic++) {
            #pragma unroll
            for (int ky = 0; ky < 3; ky++) {
                const int iy = 2 * oy + ky - 1;   // <= 31 always
                if (iy < 0) continue;
                const float* row = c1s + (ic * 32 + iy) * 19;
                float r[19];
                #pragma unroll
                for (int j = 0; j < 19; j++) r[j] = row[j];
                #pragma unroll
                for (int kx = 0; kx < 3; kx++) {
                    const float2 wv = *(const float2*)(w2s + ((ic * 3 + ky) * 3 + kx) * 64 + oc0);
                    #pragma unroll
                    for (int ox = 0; ox < 9; ox++) {
                        const float v = r[2 * ox + kx];
                        acc[0][ox] += wv.x * v;
                        acc[1][ox] += wv.y * v;
                    }
                }
            }
        }
        #pragma unroll
        for (int c = 0; c < 2; c++)
            #pragma unroll
            for (int ox = 0; ox < 9; ox++)
                c2s[((oc0 + c) * 16 + oy) * 11 + ox + 1] = fmaxf(acc[c][ox], 0.f);
    }
    __syncthreads();

    // --- stage conv3 weights over dead c1s/w2s region ---
    {
        const float4* src = (const float4*)g_w3t;
        float4* dst = (float4*)w3s;
        for (int i = tid; i < 9216; i += 512) dst[i] = src[i];
    }
    __syncthreads();

    // --- conv3: 64->64 ch, 3x3 s2 p1 -> 64x(8x5). threads 0..255 = (oc pair, oy) ---
    if (tid < 256) {
        const int oc0 = (tid >> 3) * 2;   // 0..62
        const int oy  = tid & 7;
        float acc[2][5];
        {
            const float b0 = b3[oc0], b1v = b3[oc0 + 1];
            #pragma unroll
            for (int x = 0; x < 5; x++) { acc[0][x] = b0; acc[1][x] = b1v; }
        }
        for (int ic = 0; ic < 64; ic++) {
            #pragma unroll
            for (int ky = 0; ky < 3; ky++) {
                const int iy = 2 * oy + ky - 1;   // <= 15 always
                if (iy < 0) continue;
                const float* row = c2s + (ic * 16 + iy) * 11;
                float r[11];
                #pragma unroll
                for (int j = 0; j < 11; j++) r[j] = row[j];
                #pragma unroll
                for (int kx = 0; kx < 3; kx++) {
                    const float2 wv = *(const float2*)(w3s + ((ic * 3 + ky) * 3 + kx) * 64 + oc0);
                    #pragma unroll
                    for (int ox = 0; ox < 5; ox++) {
                        const float v = r[2 * ox + kx];
                        acc[0][ox] += wv.x * v;
                        acc[1][ox] += wv.y * v;
                    }
                }
            }
        }
        #pragma unroll
        for (int c = 0; c < 2; c++)
            #pragma unroll
            for (int ox = 0; ox < 5; ox++)
                c3s[(oc0 + c) * 40 + oy * 5 + ox] = fmaxf(acc[c][ox], 0.f);
    }
    __syncthreads();

    // --- write c3 flat ---
    {
        float4* dst = (float4*)(g_c3 + (size_t)s * CNN_FLAT_);
        const float4* src = (const float4*)c3s;
        for (int i = tid; i < 640; i += 512) dst[i] = src[i];
    }
}

// ---------------- generic tiled fp32 GEMM: C = act(A @ B^T + bias [+bias2]) ----------------
__global__ void __launch_bounds__(256, 2) gemm_bias_act(
    const float* __restrict__ A, int lda,
    const float* __restrict__ B,
    const float* __restrict__ bias, const float* __restrict__ bias2,
    float* __restrict__ C, int ldc,
    int N, int K, int do_relu)
{
    __shared__ float As[16][132];
    __shared__ float Bs[16][132];
    const int m0 = blockIdx.y * 128;
    const int n0 = blockIdx.x * 128;
    const int tid = threadIdx.x;
    const int tx = tid & 15, ty = tid >> 4;

    float acc[8][8];
    #pragma unroll
    for (int i = 0; i < 8; i++)
        #pragma unroll
        for (int j = 0; j < 8; j++) acc[i][j] = 0.f;

    for (int k0 = 0; k0 < K; k0 += 16) {
        #pragma unroll
        for (int i = 0; i < 8; i++) {
            const int idx = tid + i * 256;
            const int r = idx >> 4, kk = idx & 15;
            const int k = k0 + kk;
            As[kk][r] = (k < K) ? A[(size_t)(m0 + r) * lda + k] : 0.f;
        }
        #pragma unroll
        for (int i = 0; i < 8; i++) {
            const int idx = tid + i * 256;
            const int c = idx >> 4, kk = idx & 15;
            const int k = k0 + kk;
            const int n = n0 + c;
            Bs[kk][c] = (n < N && k < K) ? B[(size_t)n * K + k] : 0.f;
        }
        __syncthreads();
        #pragma unroll
        for (int kk = 0; kk < 16; kk++) {
            float a[8], b[8];
            #pragma unroll
            for (int i = 0; i < 8; i++) a[i] = As[kk][ty * 8 + i];
            #pragma unroll
            for (int j = 0; j < 8; j++) b[j] = Bs[kk][tx * 8 + j];
            #pragma unroll
            for (int i = 0; i < 8; i++)
                #pragma unroll
                for (int j = 0; j < 8; j++) acc[i][j] += a[i] * b[j];
        }
        __syncthreads();
    }

    #pragma unroll
    for (int i = 0; i < 8; i++) {
        const int m = m0 + ty * 8 + i;
        #pragma unroll
        for (int j = 0; j < 8; j++) {
            const int n = n0 + tx * 8 + j;
            if (n < N) {
                float v = acc[i][j] + bias[n];
                if (bias2) v += bias2[n];
                if (do_relu) v = fmaxf(v, 0.f);
                C[(size_t)m * ldc + n] = v;
            }
        }
    }
}

// ---------------- LSTM recurrence: one block per batch element ----------------
// 384 of 512 gate weight-columns staged in smem, rest streamed from L2.
#define WS_G 384
#define LSTM_SMEM_FLOATS (128 * WS_G + 768)

__device__ __forceinline__ float sigf(float x) { return 1.f / (1.f + __expf(-x)); }

__global__ void __launch_bounds__(512, 1) lstm_kernel(
    const int* __restrict__ done,
    const float* __restrict__ h0, const float* __restrict__ c0,
    float* __restrict__ out_hf, float* __restrict__ out_cf)
{
    extern __shared__ float lsm[];
    float* ws = lsm;                      // [k][WS_G]
    float* hs = lsm + 128 * WS_G;
    float* cs = hs + 128;
    float* gs = cs + 128;
    const int b = blockIdx.x;
    const int tid = threadIdx.x;

    for (int i = tid; i < 128 * WS_G; i += 512) {
        const int kk = i / WS_G, g = i % WS_G;
        ws[i] = g_whhT[kk * 512 + g];
    }
    if (tid < 128) {
        hs[tid] = h0[b * 128 + tid];
        cs[tid] = c0[b * 128 + tid];
    }
    __syncthreads();

    for (int t = 0; t < T_; t++) {
        const float keep = (t == 0) ? 1.f : (done[(t - 1) * B_ + b] ? 0.f : 1.f);
        float acc = 0.f;
        if (tid < WS_G) {
            const float* wc = ws + tid;
            #pragma unroll 8
            for (int kk = 0; kk < 128; kk++) acc += wc[kk * WS_G] * hs[kk];
        } else {
            const float* wc = g_whhT + tid;
            #pragma unroll 8
            for (int kk = 0; kk < 128; kk++) acc += wc[kk * 512] * hs[kk];
        }
        gs[tid] = g_xg[((size_t)(t * B_) + b) * 512 + tid] + keep * acc;
        __syncthreads();
        if (tid < 128) {
            const float ig = sigf(gs[tid]);
            const float fg = sigf(gs[tid + 128]);
            const float gg = tanhf(gs[tid + 256]);
            const float og = sigf(gs[tid + 384]);
            const float cn = fg * (cs[tid] * keep) + ig * gg;
            const float hn = og * tanhf(cn);
            cs[tid] = cn;
            hs[tid] = hn;
            g_h[((size_t)(t * B_) + b) * 128 + tid] = hn;
        }
        __syncthreads();
    }
    if (tid < 128) {
        out_hf[b * 128 + tid] = hs[tid];
        out_cf[b * 128 + tid] = cs[tid];
    }
}

// ---------------- values head: one warp per sample ----------------
__global__ void values_kernel(const float* __restrict__ vw, const float* __restrict__ vb,
                              float* __restrict__ out)
{
    const int warp = (blockIdx.x * blockDim.x + threadIdx.x) >> 5;
    const int lane = threadIdx.x & 31;
    if (warp >= TB_) return;
    const float* h = g_h + (size_t)warp * 128;
    float p = 0.f;
    #pragma unroll
    for (int i = 0; i < 4; i++) p += h[lane + i * 32] * vw[lane + i * 32];
    #pragma unroll
    for (int o = 16; o > 0; o >>= 1) p += __shfl_xor_sync(0xffffffffu, p, o);
    if (lane == 0) out[warp] = p + vb[0];
}

// ---------------- launch ----------------
extern "C" void kernel_launch(void* const* d_in, const int* in_sizes, int n_in,
                              void* d_out, int out_size)
{
    const float* obs    = (const float*)d_in[0];
    const float* h0     = (const float*)d_in[1];
    const float* c0     = (const float*)d_in[2];
    const int*   done   = (const int*)d_in[3];
    const float* conv1w = (const float*)d_in[4];
    const float* conv1b = (const float*)d_in[5];
    const float* conv2w = (const float*)d_in[6];
    const float* conv2b = (const float*)d_in[7];
    const float* conv3w = (const float*)d_in[8];
    const float* conv3b = (const float*)d_in[9];
    const float* fcw    = (const float*)d_in[10];
    const float* fcb    = (const float*)d_in[11];
    const float* s1w    = (const float*)d_in[12];
    const float* s1b    = (const float*)d_in[13];
    const float* s2w    = (const float*)d_in[14];
    const float* s2b    = (const float*)d_in[15];
    const float* wih    = (const float*)d_in[16];
    const float* whh    = (const float*)d_in[17];
    const float* bih    = (const float*)d_in[18];
    const float* bhh    = (const float*)d_in[19];
    const float* polw   = (const float*)d_in[20];
    const float* polb   = (const float*)d_in[21];
    const float* valw   = (const float*)d_in[22];
    const float* valb   = (const float*)d_in[23];
    float* out = (float*)d_out;

    float *p_c3, *p_s1, *p_emb, *p_xg, *p_h;
    cudaGetSymbolAddress((void**)&p_c3, g_c3);
    cudaGetSymbolAddress((void**)&p_s1, g_s1);
    cudaGetSymbolAddress((void**)&p_emb, g_emb);
    cudaGetSymbolAddress((void**)&p_xg, g_xg);
    cudaGetSymbolAddress((void**)&p_h, g_h);

    // weight re-layouts
    transpose_w2<<<(18432 + 255) / 256, 256>>>(conv2w);
    transpose_w3<<<(36864 + 255) / 256, 256>>>(conv3w);
    transpose_whh<<<(512 * 128 + 255) / 256, 256>>>(whh);

    // conv stack
    cudaFuncSetAttribute(conv_kernel, cudaFuncAttributeMaxDynamicSharedMemorySize,
                         CONV_SMEM_FLOATS * 4);
    conv_kernel<<<TB_, 512, CONV_SMEM_FLOATS * 4>>>(obs, conv1w, conv1b, conv2b, conv3b);

    // scalar MLP: s1 then s2 -> emb cols [128,192)
    gemm_bias_act<<<dim3(1, TB_ / 128), 256>>>(obs, OBS_DIM_, s1w, s1b, nullptr,
                                               p_s1, 64, 64, SCALAR_DIM_, 1);
    gemm_bias_act<<<dim3(1, TB_ / 128), 256>>>(p_s1, 64, s2w, s2b, nullptr,
                                               p_emb + 128, EMB_, 64, 64, 1);

    // fc: c3 -> emb cols [0,128)
    gemm_bias_act<<<dim3(1, TB_ / 128), 256>>>(p_c3, CNN_FLAT_, fcw, fcb, nullptr,
                                               p_emb, EMB_, 128, CNN_FLAT_, 1);

    // xg = emb @ w_ih^T + b_ih + b_hh
    gemm_bias_act<<<dim3(4, TB_ / 128), 256>>>(p_emb, EMB_, wih, bih, bhh,
                                               p_xg, 512, 512, EMB_, 0);

    // recurrence
    cudaFuncSetAttribute(lstm_kernel, cudaFuncAttributeMaxDynamicSharedMemorySize,
                         LSTM_SMEM_FLOATS * 4);
    lstm_kernel<<<B_, 512, LSTM_SMEM_FLOATS * 4>>>(done, h0, c0, out + OUT_HF_, out + OUT_CF_);

    // heads
    gemm_bias_act<<<dim3((N_ACT_ + 127) / 128, TB_ / 128), 256>>>(
        p_h, HID_, polw, polb, nullptr, out + OUT_LOGITS_, N_ACT_, N_ACT_, HID_, 0);
    values_kernel<<<TB_ / 8, 256>>>(valw, valb, out + OUT_VALUES_);
}